// round 1
// baseline (speedup 1.0000x reference)
#include <cuda_runtime.h>
#include <cuda_bf16.h>
#include <math.h>

// Problem constants
#define T_TOK   8192          // BATCH*SEQ
#define DMODEL  1024
#define NEXP    8
#define TOPK    2
#define DFF     4096
#define PAIRS   (T_TOK*TOPK)      // 16384
#define SEG_AL  64                // expert segment alignment (== BM)
#define PMAX    16896             // 16384 + 8*64 headroom, multiple of 64

// ---------------- device globals (scratch; no allocations allowed) ----------
__device__ int   d_tok_expert[PAIRS];
__device__ float d_tok_weight[PAIRS];
__device__ int   d_counts[NEXP];
__device__ int   d_offsets[NEXP + 1];
__device__ int   d_cursor[NEXP];
__device__ int   d_pair_token[PMAX];
__device__ float d_pair_weight[PMAX];
__device__ float d_h[(size_t)PMAX * DFF];   // GELU(x@W1+b1) scratch, ~277 MB

// ---------------- init ------------------------------------------------------
__global__ void init_route_kernel() {
    int i = blockIdx.x * blockDim.x + threadIdx.x;
    if (i < PMAX) d_pair_token[i] = -1;
    if (i < NEXP) { d_counts[i] = 0; }
}

// ---------------- gating ----------------------------------------------------
__global__ void gate_kernel(const float* __restrict__ x,
                            const float* __restrict__ Wg,
                            const float* __restrict__ bg,
                            float* __restrict__ gate_out) {
    int warp = (blockIdx.x * blockDim.x + threadIdx.x) >> 5;
    int lane = threadIdx.x & 31;
    if (warp >= T_TOK) return;

    const float* xr = x + (size_t)warp * DMODEL;
    float acc[NEXP];
#pragma unroll
    for (int e = 0; e < NEXP; e++) acc[e] = 0.f;

    for (int d = lane; d < DMODEL; d += 32) {
        float xv = xr[d];
        const float4* wr = (const float4*)(Wg + (size_t)d * NEXP);
        float4 w0 = wr[0], w1 = wr[1];
        acc[0] += xv * w0.x; acc[1] += xv * w0.y;
        acc[2] += xv * w0.z; acc[3] += xv * w0.w;
        acc[4] += xv * w1.x; acc[5] += xv * w1.y;
        acc[6] += xv * w1.z; acc[7] += xv * w1.w;
    }
#pragma unroll
    for (int e = 0; e < NEXP; e++)
#pragma unroll
        for (int o = 16; o; o >>= 1)
            acc[e] += __shfl_xor_sync(0xFFFFFFFFu, acc[e], o);

    if (lane == 0) {
        float lg[NEXP], p[NEXP];
        float mx = -1e30f;
#pragma unroll
        for (int e = 0; e < NEXP; e++) { lg[e] = acc[e] + bg[e]; mx = fmaxf(mx, lg[e]); }
        float s = 0.f;
#pragma unroll
        for (int e = 0; e < NEXP; e++) { p[e] = expf(lg[e] - mx); s += p[e]; }
        float inv = 1.f / s;
#pragma unroll
        for (int e = 0; e < NEXP; e++) p[e] *= inv;

        // top-2, jax.lax.top_k tiebreak = lowest index first (strict >)
        int i1 = 0;
#pragma unroll
        for (int e = 1; e < NEXP; e++) if (p[e] > p[i1]) i1 = e;
        int i2 = -1;
#pragma unroll
        for (int e = 0; e < NEXP; e++) {
            if (e == i1) continue;
            if (i2 < 0 || p[e] > p[i2]) i2 = e;
        }

        float* go = gate_out + (size_t)warp * NEXP;
#pragma unroll
        for (int e = 0; e < NEXP; e++) go[e] = lg[e];

        d_tok_expert[warp * 2 + 0] = i1;  d_tok_weight[warp * 2 + 0] = p[i1];
        d_tok_expert[warp * 2 + 1] = i2;  d_tok_weight[warp * 2 + 1] = p[i2];
        atomicAdd(&d_counts[i1], 1);
        atomicAdd(&d_counts[i2], 1);
    }
}

// ---------------- routing prefix + scatter ----------------------------------
__global__ void offsets_kernel() {
    int off = 0;
    for (int e = 0; e < NEXP; e++) {
        d_offsets[e] = off;
        d_cursor[e]  = off;
        off += (d_counts[e] + SEG_AL - 1) & ~(SEG_AL - 1);
    }
    d_offsets[NEXP] = off;
}

__global__ void scatter_kernel() {
    int pidx = blockIdx.x * blockDim.x + threadIdx.x;
    if (pidx >= PAIRS) return;
    int e = d_tok_expert[pidx];
    int pos = atomicAdd(&d_cursor[e], 1);
    d_pair_token[pos]  = pidx >> 1;
    d_pair_weight[pos] = d_tok_weight[pidx];
}

// ---------------- GEMM tiles -------------------------------------------------
#define BM 64
#define BN 64
#define BK 16

__device__ __forceinline__ float gelu_exact(float h) {
    return 0.5f * h * (1.0f + erff(h * 0.70710678118654752f));
}

// h = gelu(x[token_rows] @ W1[e] + b1[e]) -> d_h
__global__ __launch_bounds__(256) void gemm1_kernel(const float* __restrict__ x,
                                                    const float* __restrict__ W1,
                                                    const float* __restrict__ b1) {
    __shared__ float As[BK][BM];
    __shared__ float Bs[BK][BN];

    int row0 = blockIdx.y * BM;
    int P = d_offsets[NEXP];
    if (row0 >= P) return;
    int e = 0;
    while (row0 >= d_offsets[e + 1]) e++;

    int n0  = blockIdx.x * BN;
    int tid = threadIdx.x;

    int ar = tid >> 2, av = tid & 3;          // A loader: row, k-vec
    int t  = d_pair_token[row0 + ar];
    const float* xrow = (t >= 0) ? x + (size_t)t * DMODEL : x;

    int bk = tid >> 4, bv = tid & 15;         // B loader: k-row, n-vec
    const float* Bbase = W1 + (size_t)e * DMODEL * DFF + n0 + bv * 4;

    int tx = tid & 15, ty = tid >> 4;         // compute: 4x4 tile
    float acc[4][4];
#pragma unroll
    for (int i = 0; i < 4; i++)
#pragma unroll
        for (int j = 0; j < 4; j++) acc[i][j] = 0.f;

    for (int k0 = 0; k0 < DMODEL; k0 += BK) {
        float4 a = (t >= 0) ? *(const float4*)(xrow + k0 + av * 4)
                            : make_float4(0.f, 0.f, 0.f, 0.f);
        As[av * 4 + 0][ar] = a.x;
        As[av * 4 + 1][ar] = a.y;
        As[av * 4 + 2][ar] = a.z;
        As[av * 4 + 3][ar] = a.w;

        *(float4*)&Bs[bk][bv * 4] =
            *(const float4*)(Bbase + (size_t)(k0 + bk) * DFF);

        __syncthreads();
#pragma unroll
        for (int kk = 0; kk < BK; kk++) {
            float4 a4 = *(const float4*)&As[kk][ty * 4];
            float4 b4 = *(const float4*)&Bs[kk][tx * 4];
            float av_[4] = {a4.x, a4.y, a4.z, a4.w};
            float bv_[4] = {b4.x, b4.y, b4.z, b4.w};
#pragma unroll
            for (int i = 0; i < 4; i++)
#pragma unroll
                for (int j = 0; j < 4; j++) acc[i][j] += av_[i] * bv_[j];
        }
        __syncthreads();
    }

    const float* b1e = b1 + (size_t)e * DFF + n0 + tx * 4;
#pragma unroll
    for (int i = 0; i < 4; i++) {
        size_t r = row0 + ty * 4 + i;
        float* hr = d_h + r * DFF + n0 + tx * 4;
#pragma unroll
        for (int j = 0; j < 4; j++)
            hr[j] = gelu_exact(acc[i][j] + b1e[j]);
    }
}

// out[token] += weight * (h @ W2[e] + b2[e])
__global__ __launch_bounds__(256) void gemm2_kernel(const float* __restrict__ W2,
                                                    const float* __restrict__ b2,
                                                    float* __restrict__ out) {
    __shared__ float As[BK][BM];
    __shared__ float Bs[BK][BN];

    int row0 = blockIdx.y * BM;
    int P = d_offsets[NEXP];
    if (row0 >= P) return;
    int e = 0;
    while (row0 >= d_offsets[e + 1]) e++;

    int n0  = blockIdx.x * BN;
    int tid = threadIdx.x;

    int ar = tid >> 2, av = tid & 3;
    const float* hrow = d_h + (size_t)(row0 + ar) * DFF;

    int bk = tid >> 4, bv = tid & 15;
    const float* Bbase = W2 + (size_t)e * DFF * DMODEL + n0 + bv * 4;

    int tx = tid & 15, ty = tid >> 4;
    float acc[4][4];
#pragma unroll
    for (int i = 0; i < 4; i++)
#pragma unroll
        for (int j = 0; j < 4; j++) acc[i][j] = 0.f;

    for (int k0 = 0; k0 < DFF; k0 += BK) {
        float4 a = *(const float4*)(hrow + k0 + av * 4);
        As[av * 4 + 0][ar] = a.x;
        As[av * 4 + 1][ar] = a.y;
        As[av * 4 + 2][ar] = a.z;
        As[av * 4 + 3][ar] = a.w;

        *(float4*)&Bs[bk][bv * 4] =
            *(const float4*)(Bbase + (size_t)(k0 + bk) * DMODEL);

        __syncthreads();
#pragma unroll
        for (int kk = 0; kk < BK; kk++) {
            float4 a4 = *(const float4*)&As[kk][ty * 4];
            float4 b4 = *(const float4*)&Bs[kk][tx * 4];
            float av_[4] = {a4.x, a4.y, a4.z, a4.w};
            float bv_[4] = {b4.x, b4.y, b4.z, b4.w};
#pragma unroll
            for (int i = 0; i < 4; i++)
#pragma unroll
                for (int j = 0; j < 4; j++) acc[i][j] += av_[i] * bv_[j];
        }
        __syncthreads();
    }

    const float* b2e = b2 + (size_t)e * DMODEL + n0 + tx * 4;
#pragma unroll
    for (int i = 0; i < 4; i++) {
        int r = row0 + ty * 4 + i;
        int t = d_pair_token[r];
        if (t < 0) continue;
        float w = d_pair_weight[r];
        float* orow = out + (size_t)t * DMODEL + n0 + tx * 4;
#pragma unroll
        for (int j = 0; j < 4; j++)
            atomicAdd(&orow[j], w * (acc[i][j] + b2e[j]));
    }
}

// ---------------- launch -----------------------------------------------------
extern "C" void kernel_launch(void* const* d_in, const int* in_sizes, int n_in,
                              void* d_out, int out_size) {
    const float* x  = (const float*)d_in[0];
    const float* Wg = (const float*)d_in[1];
    const float* bg = (const float*)d_in[2];
    const float* W1 = (const float*)d_in[3];
    const float* b1 = (const float*)d_in[4];
    const float* W2 = (const float*)d_in[5];
    const float* b2 = (const float*)d_in[6];

    float* out      = (float*)d_out;
    float* gate_out = out + (size_t)T_TOK * DMODEL;   // second output: gate_logits

    // zero the combine target (each element gets exactly 2 atomic adds)
    cudaMemsetAsync(out, 0, (size_t)T_TOK * DMODEL * sizeof(float));

    init_route_kernel<<<(PMAX + 255) / 256, 256>>>();
    gate_kernel<<<(T_TOK * 32) / 256, 256>>>(x, Wg, bg, gate_out);
    offsets_kernel<<<1, 1>>>();
    scatter_kernel<<<(PAIRS + 255) / 256, 256>>>();

    dim3 g1(DFF / BN, PMAX / BM);     // (64, 264)
    dim3 g2(DMODEL / BN, PMAX / BM);  // (16, 264)
    gemm1_kernel<<<g1, 256>>>(x, W1, b1);
    gemm2_kernel<<<g2, 256>>>(W2, b2, out);
}